// round 6
// baseline (speedup 1.0000x reference)
#include <cuda_runtime.h>
#include <cstdint>

#define BB 4
#define NN 8192
#define FF 64
#define EE 65536
#define KK 4096
#define NW 256   // NN/32
#define KW 128   // KK/32
#define TGT (NN-KK)
#define FULLM 0xffffffffu
#define NBLK 128   // radix sort tiles per batch (512 keys each)
#define SORTBLKS (NBLK * BB)

// ---------------- device scratch (static; no allocations) ----------------
__device__ unsigned long long g_keys[2][BB][EE];   // ping-pong
__device__ unsigned char g_ok[BB][EE];
__device__ unsigned g_sedge[BB][EE];               // packed (a | b<<13 | ok<<26) sorted
__device__ float g_vn[BB][NN];
__device__ int g_mask[BB][NN];
__device__ int g_m[BB][NN];
__device__ int g_rank[BB][NN];
__device__ int g_gstart[BB][KK + 1];
__device__ unsigned short g_gsrc[BB][NN];
__device__ unsigned g_hist[BB][256 * NBLK];
__device__ unsigned g_histS[BB][256 * NBLK];
__device__ unsigned g_barC[12];                    // grid barriers (reset by k_keys)
__device__ unsigned g_Ab[BB][NN][NW];              // 32 MB : row-major bits of A
__device__ unsigned g_G1[BB][KK][NW];              // 16 MB : row-merged
__device__ unsigned g_G1T[BB][NN][KW];             // 16 MB : transpose of G1
__device__ unsigned g_G2[BB][KK][KW];              // 8 MB  : col-merged (transposed final)
__device__ unsigned g_M2[BB][KK][KW];              // 8 MB  : final K x K bits (row-major)

// ---------------- utils ----------------
__device__ __forceinline__ unsigned warpScanIncl(unsigned v) {
    int lane = threadIdx.x & 31;
#pragma unroll
    for (int o = 1; o < 32; o <<= 1) {
        unsigned n = __shfl_up_sync(FULLM, v, o);
        if (lane >= o) v += n;
    }
    return v;
}

__device__ __forceinline__ unsigned blockScanExcl1024(unsigned v, unsigned* s_tmp, unsigned* total) {
    int tid = threadIdx.x, lane = tid & 31, wid = tid >> 5;
    __syncthreads();
    unsigned inc = warpScanIncl(v);
    if (lane == 31) s_tmp[wid] = inc;
    __syncthreads();
    if (wid == 0) {
        unsigned w = s_tmp[lane];
        unsigned wi = warpScanIncl(w);
        s_tmp[lane] = wi - w;
        if (lane == 31) s_tmp[32] = wi;
    }
    __syncthreads();
    *total = s_tmp[32];
    return inc - v + s_tmp[wid];
}

// grid barrier across SORTBLKS blocks; counters pre-zeroed by k_keys each replay
__device__ __forceinline__ void gridBar(int id) {
    __syncthreads();
    if (threadIdx.x == 0) {
        __threadfence();
        atomicAdd(&g_barC[id], 1u);
        while (((volatile unsigned*)g_barC)[id] < (unsigned)SORTBLKS) { }
        __threadfence();
    }
    __syncthreads();
}

// ---------------- 1. vertex squared norms (XLA-order) + init m ----------------
__global__ void k_vnorm(const float* __restrict__ image) {
    int idx = blockIdx.x * blockDim.x + threadIdx.x;
    if (idx >= BB * NN) return;
    const float* row = image + (size_t)idx * FF;
    float p[32];
#pragma unroll
    for (int l = 0; l < 32; l++) {
        float a = row[l], c = row[l + 32];
        p[l] = __fadd_rn(__fmul_rn(a, a), __fmul_rn(c, c));
    }
#pragma unroll
    for (int off = 16; off >= 1; off >>= 1) {
#pragma unroll
        for (int l = 0; l < 16; l++) {
            if (l < off) p[l] = __fadd_rn(p[l], p[l + off]);
        }
    }
    g_vn[0][idx] = p[0];
    g_m[0][idx] = idx & (NN - 1);
}

// ---------------- 2. keys + boundary ok + barrier reset ----------------
__global__ void k_keys(const int* __restrict__ edges, const float* __restrict__ vs) {
    int idx = blockIdx.x * blockDim.x + threadIdx.x;
    if (blockIdx.x == 0 && threadIdx.x < 12) g_barC[threadIdx.x] = 0;  // reset grid barriers
    int b = idx >> 16, e = idx & (EE - 1);
    if (b >= BB) return;
    int a = edges[(size_t)b * 2 * EE + e];
    int v1 = edges[(size_t)b * 2 * EE + EE + e];
    float c = __fadd_rn(g_vn[b][a], g_vn[b][v1]);
    g_keys[0][b][e] = ((unsigned long long)__float_as_uint(c) << 32) | (unsigned)e;
    float ax = vs[((size_t)b * NN + a) * 2 + 0], ay = vs[((size_t)b * NN + a) * 2 + 1];
    float bx = vs[((size_t)b * NN + v1) * 2 + 0], by = vs[((size_t)b * NN + v1) * 2 + 1];
    bool bndA = (ax < 0.05f) | (ax > 0.95f) | (ay < 0.05f) | (ay > 0.95f);
    bool bndB = (bx < 0.05f) | (bx > 0.95f) | (by < 0.05f) | (by > 0.95f);
    g_ok[b][e] = (unsigned char)(!(bndA | bndB));
}

// ---------------- 3. fused 4-pass stable LSD radix sort (single kernel) ----------------
// 512 blocks x 256 thr, all co-resident (1 wave). Grid barriers between phases.
// Last pass scatters packed sedge words directly (fused gather).
__global__ void __launch_bounds__(256, 4) k_sortall(const int* __restrict__ edges) {
    __shared__ unsigned s_h[256];
    __shared__ unsigned s_wcnt[8 * 256];
    __shared__ unsigned s_pre[8 * 256];
    __shared__ unsigned s_base[256];
    __shared__ unsigned s_w[9];
    int gid = blockIdx.x;
    int b = gid >> 7, blk = gid & 127;
    int t = threadIdx.x, lane = t & 31, w = t >> 5;
    int barid = 0;
#pragma unroll 1
    for (int p = 0; p < 4; p++) {
        const unsigned long long* src = g_keys[p & 1][b];
        unsigned long long* dst = g_keys[(p + 1) & 1][b];
        int sh = 32 + 8 * p;
        // --- count ---
        s_h[t] = 0;
        __syncthreads();
        unsigned long long k0 = src[blk * 512 + t], k1 = src[blk * 512 + 256 + t];
        atomicAdd(&s_h[(unsigned)(k0 >> sh) & 255u], 1u);
        atomicAdd(&s_h[(unsigned)(k1 >> sh) & 255u], 1u);
        __syncthreads();
        g_hist[b][t * NBLK + blk] = s_h[t];
        gridBar(barid++);
        // --- scan (block blk==0 of each batch scans its 32768 hist entries) ---
        if (blk == 0) {
            unsigned base = t * 128, sum = 0;
            for (int i = 0; i < 128; i++) sum += g_hist[b][base + i];
            unsigned inc = warpScanIncl(sum);
            if (lane == 31) s_w[w] = inc;
            __syncthreads();
            if (w == 0) {
                unsigned v8 = (lane < 8) ? s_w[lane] : 0;
                unsigned wi = warpScanIncl(v8);
                if (lane < 8) s_w[lane] = wi - v8;
            }
            __syncthreads();
            unsigned run = inc - sum + s_w[w];
            for (int i = 0; i < 128; i++) {
                unsigned h = g_hist[b][base + i];
                g_histS[b][base + i] = run; run += h;
            }
        }
        gridBar(barid++);
        // --- stable scatter ---
#pragma unroll
        for (int k = 0; k < 8; k++) s_wcnt[k * 256 + t] = 0;
        s_base[t] = g_histS[b][t * NBLK + blk];
        __syncthreads();
        unsigned long long kk[2] = { k0, k1 };
#pragma unroll
        for (int i = 0; i < 2; i++) {
            unsigned d = (unsigned)(kk[i] >> sh) & 255u;
            unsigned m = __match_any_sync(FULLM, d);
            unsigned below = (1u << lane) - 1u;
            unsigned rw = __popc(m & below);
            if (rw == 0) s_wcnt[w * 256 + d] = __popc(m);
            __syncthreads();
            unsigned run = s_base[t];
#pragma unroll
            for (int w2 = 0; w2 < 8; w2++) { s_pre[w2 * 256 + t] = run; run += s_wcnt[w2 * 256 + t]; }
            s_base[t] = run;
            __syncthreads();
            unsigned pos = s_pre[w * 256 + d] + rw;
            if (p < 3) {
                dst[pos] = kk[i];
            } else {
                unsigned eid = (unsigned)(kk[i] & 0xffffffffu);
                unsigned a = (unsigned)edges[(size_t)b * 2 * EE + eid];
                unsigned v1 = (unsigned)edges[(size_t)b * 2 * EE + EE + eid];
                g_sedge[b][pos] = a | (v1 << 13) | ((unsigned)g_ok[b][eid] << 26);
            }
            if (rw == 0) s_wcnt[w * 256 + d] = 0;
            __syncthreads();
        }
        gridBar(barid++);
    }
}

// ---------------- 4. greedy collapse: match_any + epoch tags, involved-only fallback ----
__global__ void k_greedy() {
    __shared__ unsigned char s_mask[NN];
    __shared__ unsigned short s_tagA[NN];
    __shared__ unsigned short s_tagB[NN];
    int b = blockIdx.x, lane = threadIdx.x;
    for (int i = lane; i < NN; i += 32) { s_mask[i] = 1; s_tagA[i] = 0xFFFF; s_tagB[i] = 0xFFFF; }
    __syncwarp();
    int nk = 0;
    const int W = EE / 32;
    unsigned cur = g_sedge[b][lane];
    for (int w = 0; w < W; w++) {
        unsigned nxt = (w + 1 < W) ? g_sedge[b][(w + 1) * 32 + lane] : 0u;
        int a = cur & 8191, b2 = (cur >> 13) & 8191, okv = (cur >> 26) & 1;
        int tent = okv && s_mask[a] && s_mask[b2];
        unsigned T = __ballot_sync(FULLM, tent);
        if (T) {
            unsigned short w16 = (unsigned short)w;
            unsigned vb = tent ? (unsigned)b2 : (0x10000u + lane);
            unsigned mb = __match_any_sync(FULLM, vb);
            if (tent) { s_tagA[a] = w16; s_tagB[b2] = w16; }
            __syncwarp();
            int flag = 0;
            if (tent) {
                flag = (mb != (1u << lane)) ||          // duplicate kill target
                       (s_tagA[b2] == w16) ||           // my b is someone's absorber
                       (s_tagB[a] == w16);              // my a is someone's kill target
            }
            unsigned involved = __ballot_sync(FULLM, flag);
            unsigned below = (1u << lane) - 1u;
            unsigned acc = 0;
            int cnt = __popc(T);
            if (!involved && nk + cnt <= TGT) {
                acc = T; nk += cnt;
            } else if (!involved) {
                int rem = TGT - nk;
                acc = __ballot_sync(FULLM, tent && (__popc(T & below) < rem));
                nk = TGT;
            } else if (nk + cnt <= TGT) {
                unsigned clean = T & ~involved;
                acc = clean; nk += __popc(clean);
                unsigned TT = T & involved;
                while (TT) {
                    int t2 = __ffs(TT) - 1; TT &= TT - 1;
                    int at = __shfl_sync(FULLM, a, t2);
                    int bt = __shfl_sync(FULLM, b2, t2);
                    unsigned conf = __ballot_sync(FULLM, ((acc >> lane) & 1) && (b2 == at || b2 == bt));
                    if (!conf) { acc |= 1u << t2; nk++; }
                }
            } else {
                unsigned TT = T;
                while (TT) {
                    int t2 = __ffs(TT) - 1; TT &= TT - 1;
                    int at = __shfl_sync(FULLM, a, t2);
                    int bt = __shfl_sync(FULLM, b2, t2);
                    unsigned conf = __ballot_sync(FULLM, ((acc >> lane) & 1) && (b2 == at || b2 == bt));
                    if (!conf && nk < TGT) { acc |= 1u << t2; nk++; }
                }
            }
            if ((acc >> lane) & 1) { s_mask[b2] = 0; g_m[b][b2] = a; }
            __syncwarp();
            if (nk >= TGT) break;
        }
        cur = nxt;
    }
    for (int i = lane; i < NN; i += 32) g_mask[b][i] = s_mask[i];
}

// ---------------- 5. alive ranks + group CSR ----------------
__global__ void __launch_bounds__(1024) k_compact() {
    __shared__ unsigned s_tmp[33];
    __shared__ int s_cnt[KK];
    __shared__ int s_cur[KK];
    int b = blockIdx.x, tid = threadIdx.x;
    int base = tid * 8;
    unsigned mk[8]; unsigned c = 0;
#pragma unroll
    for (int i = 0; i < 8; i++) { mk[i] = (unsigned)g_mask[b][base + i]; c += mk[i]; }
    unsigned tot;
    unsigned ex = blockScanExcl1024(c, s_tmp, &tot);
    int run = (int)ex;
#pragma unroll
    for (int i = 0; i < 8; i++) { g_rank[b][base + i] = run; run += (int)mk[i]; }
    __syncthreads();
    for (int r = tid; r < KK; r += 1024) s_cnt[r] = 0;
    __syncthreads();
    for (int j = tid; j < NN; j += 1024) {
        int t = g_m[b][j];
        if (g_mask[b][t]) { int r = g_rank[b][t]; if (r < KK) atomicAdd(&s_cnt[r], 1); }
    }
    __syncthreads();
    int i4 = tid * 4; unsigned cv[4]; unsigned sum = 0;
#pragma unroll
    for (int i = 0; i < 4; i++) { cv[i] = (unsigned)s_cnt[i4 + i]; sum += cv[i]; }
    unsigned tot2;
    unsigned ex2 = blockScanExcl1024(sum, s_tmp, &tot2);
    int run2 = (int)ex2;
#pragma unroll
    for (int i = 0; i < 4; i++) { g_gstart[b][i4 + i] = run2; s_cur[i4 + i] = run2; run2 += (int)cv[i]; }
    if (tid == 1023) g_gstart[b][KK] = run2;
    __syncthreads();
    for (int j = tid; j < NN; j += 1024) {
        int t = g_m[b][j];
        if (g_mask[b][t]) {
            int r = g_rank[b][t];
            if (r < KK) { int pos = atomicAdd(&s_cur[r], 1); g_gsrc[b][pos] = (unsigned short)j; }
        }
    }
}

// ---------------- 6. pack A (f32 0/1) -> row-major bits via warp ballot ----------------
__global__ void __launch_bounds__(256) k_pack(const float* __restrict__ A) {
    int gw = (blockIdx.x * 256 + threadIdx.x) >> 5;
    int lane = threadIdx.x & 31;
    const float* base = A + (size_t)gw * 1024;
    unsigned myw = 0;
#pragma unroll
    for (int t = 0; t < 32; t++) {
        float v = base[t * 32 + lane];
        unsigned bal = __ballot_sync(FULLM, v != 0.0f);
        if (lane == t) myw = bal;
    }
    ((unsigned*)g_Ab)[(size_t)gw * 32 + lane] = myw;
}

// ---------------- 7. G1[r] = OR of A-bit rows in group(r)  (row merge) ----------------
__global__ void __launch_bounds__(1024) k_G1() {
    int b = blockIdx.y;
    int c = blockIdx.x * 4 + (threadIdx.x >> 8);
    int w = threadIdx.x & 255;
    int s = g_gstart[b][c], e = g_gstart[b][c + 1];
    unsigned v = 0;
    for (int i = s; i < e; i++) v |= g_Ab[b][g_gsrc[b][i]][w];
    g_G1[b][c][w] = v;
}

// ---------------- 8. bit transpose G1 (K x N) -> G1T (N x K) ----------------
__global__ void __launch_bounds__(1024) k_transT() {
    __shared__ __align__(16) unsigned wt[256 * 5];
    __shared__ __align__(16) unsigned outS[1024];
    int b = blockIdx.z, ct = blockIdx.y, jt = blockIdx.x;
    int tid = threadIdx.x;
    {
        int r = tid >> 2, w4 = tid & 3;
        wt[r * 5 + w4] = g_G1[b][ct * 256 + r][jt * 4 + w4];
    }
    __syncthreads();
    int w = tid >> 5, lane = tid & 31;
    int jw = w >> 3, iw = w & 7;
    unsigned s = wt[(iw * 32 + lane) * 5 + jw];
    unsigned myword = 0;
#pragma unroll 1
    for (int k = 0; k < 32; k++) {
        unsigned bt = __ballot_sync(FULLM, (s >> k) & 1);
        if (lane == k) myword = bt;
    }
    outS[(jw * 32 + lane) * 8 + iw] = myword;
    __syncthreads();
    int j = tid >> 3, ww = tid & 7;
    g_G1T[b][jt * 128 + j][ct * 8 + ww] = outS[tid];
}

// ---------------- 9. G2[c] = OR of G1T rows in group(c)  (col merge) ----------------
__global__ void __launch_bounds__(1024) k_G2() {
    int b = blockIdx.y;
    int r = blockIdx.x * 8 + (threadIdx.x >> 7);
    int w = threadIdx.x & 127;
    int s = g_gstart[b][r], e = g_gstart[b][r + 1];
    unsigned v = 0;
    for (int i = s; i < e; i++) v |= g_G1T[b][g_gsrc[b][i]][w];
    g_G2[b][r][w] = v;
}

// ---------------- 10. final K x K bit transpose: G2 -> M2 ----------------
__global__ void __launch_bounds__(1024) k_transKK() {
    __shared__ __align__(16) unsigned wt[256 * 5];
    __shared__ __align__(16) unsigned outS[1024];
    int b = blockIdx.z, ct = blockIdx.y, jt = blockIdx.x;
    int tid = threadIdx.x;
    {
        int r = tid >> 2, w4 = tid & 3;
        wt[r * 5 + w4] = g_G2[b][ct * 256 + r][jt * 4 + w4];
    }
    __syncthreads();
    int w = tid >> 5, lane = tid & 31;
    int jw = w >> 3, iw = w & 7;
    unsigned s = wt[(iw * 32 + lane) * 5 + jw];
    unsigned myword = 0;
#pragma unroll 1
    for (int k = 0; k < 32; k++) {
        unsigned bt = __ballot_sync(FULLM, (s >> k) & 1);
        if (lane == k) myword = bt;
    }
    outS[(jw * 32 + lane) * 8 + iw] = myword;
    __syncthreads();
    int j = tid >> 3, ww = tid & 7;
    g_M2[b][jt * 128 + j][ct * 8 + ww] = outS[tid];
}

// ---------------- 11. expand bits -> float (diag cleared) + pooled features ----------
__global__ void k_expandfeat(const float* __restrict__ image, float* __restrict__ out) {
    int b = blockIdx.y;
    if (blockIdx.x < 16384) {
        int idx = blockIdx.x * 256 + threadIdx.x;
        int r = idx >> 10;
        int c4 = (idx & 1023) << 2;
        unsigned wv = g_M2[b][r][c4 >> 5];
        int sh = c4 & 31;
        float4 o;
        o.x = (((wv >> (sh + 0)) & 1) && (r != c4 + 0)) ? 1.f : 0.f;
        o.y = (((wv >> (sh + 1)) & 1) && (r != c4 + 1)) ? 1.f : 0.f;
        o.z = (((wv >> (sh + 2)) & 1) && (r != c4 + 2)) ? 1.f : 0.f;
        o.w = (((wv >> (sh + 3)) & 1) && (r != c4 + 3)) ? 1.f : 0.f;
        ((float4*)out)[((size_t)b * KK + r) * (KK / 4) + (idx & 1023)] = o;
    } else {
        int idx = (blockIdx.x - 16384) * 256 + threadIdx.x;
        int f = idx & (FF - 1);
        int r = idx >> 6;
        int s = g_gstart[b][r], e = g_gstart[b][r + 1];
        float acc = 0.f;
        for (int i = s; i < e; i++) {
            int j = g_gsrc[b][i];
            acc += image[((size_t)b * NN + j) * FF + f];
        }
        out[(size_t)BB * KK * KK + ((size_t)b * KK + r) * FF + f] = acc;
    }
}

// ---------------- launch ----------------
extern "C" void kernel_launch(void* const* d_in, const int* in_sizes, int n_in,
                              void* d_out, int out_size) {
    const float* adj = (const float*)d_in[0];
    const float* image = (const float*)d_in[1];
    const float* vs = (const float*)d_in[2];
    const int* edges = (const int*)d_in[3];
    float* out = (float*)d_out;

    static cudaStream_t s1 = nullptr;
    static cudaEvent_t evF = nullptr, evJ = nullptr;
    if (!s1) {
        cudaStreamCreateWithFlags(&s1, cudaStreamNonBlocking);
        cudaEventCreateWithFlags(&evF, cudaEventDisableTiming);
        cudaEventCreateWithFlags(&evJ, cudaEventDisableTiming);
    }

    // record fork point first: pack's graph dependency = capture start (full overlap),
    // even though its submission happens later (keeps greedy as 4th submitted launch).
    cudaEventRecord(evF, 0);

    k_vnorm<<<(BB * NN) / 256, 256>>>(image);                 // #1
    k_keys<<<(BB * EE) / 256, 256>>>(edges, vs);              // #2 (also resets barriers)
    k_sortall<<<SORTBLKS, 256>>>(edges);                      // #3
    k_greedy<<<BB, 32>>>();                                   // #4  <- ncu sample target

    cudaStreamWaitEvent(s1, evF, 0);
    k_pack<<<32768, 256, 0, s1>>>(adj);                       // #5 (runs from graph start)

    k_compact<<<BB, 1024>>>();                                // #6

    cudaEventRecord(evJ, s1);
    cudaStreamWaitEvent(0, evJ, 0);

    k_G1<<<dim3(KK / 4, BB), 1024>>>();
    k_transT<<<dim3(NN / 128, KK / 256, BB), 1024>>>();
    k_G2<<<dim3(KK / 8, BB), 1024>>>();
    k_transKK<<<dim3(KK / 128, KK / 256, BB), 1024>>>();
    k_expandfeat<<<dim3(16384 + (KK * FF) / 256, BB), 256>>>(image, out);
}

// round 9
// speedup vs baseline: 1.5166x; 1.5166x over previous
#include <cuda_runtime.h>
#include <cstdint>

#define BB 4
#define NN 8192
#define FF 64
#define EE 65536
#define KK 4096
#define NW 256   // NN/32
#define KW 128   // KK/32
#define TGT (NN-KK)
#define FULLM 0xffffffffu
#define NBLK 128   // radix sort tiles per batch (512 keys each)

// ---------------- device scratch (static; no allocations) ----------------
__device__ unsigned long long g_keys[2][BB][EE];   // ping-pong
__device__ unsigned char g_ok[BB][EE];
__device__ unsigned g_sedge[BB][EE];               // packed (a | b<<13 | ok<<26), interior-first sorted
__device__ float g_vn[BB][NN];
__device__ int g_mask[BB][NN];
__device__ int g_m[BB][NN];
__device__ int g_rank[BB][NN];
__device__ int g_gstart[BB][KK + 1];
__device__ unsigned short g_gsrc[BB][NN];
__device__ unsigned g_hist[BB][256 * NBLK];
__device__ unsigned g_histS[BB][256 * NBLK];
__device__ unsigned g_Ab[BB][NN][NW];              // 32 MB : row-major bits of A
__device__ unsigned g_G1[BB][KK][NW];              // 16 MB : row-merged
__device__ unsigned g_G1T[BB][NN][KW];             // 16 MB : transpose of G1
__device__ unsigned g_G2[BB][KK][KW];              // 8 MB  : col-merged (transposed final)
__device__ unsigned g_M2[BB][KK][KW];              // 8 MB  : final K x K bits (row-major)

// ---------------- utils ----------------
__device__ __forceinline__ unsigned warpScanIncl(unsigned v) {
    int lane = threadIdx.x & 31;
#pragma unroll
    for (int o = 1; o < 32; o <<= 1) {
        unsigned n = __shfl_up_sync(FULLM, v, o);
        if (lane >= o) v += n;
    }
    return v;
}

__device__ __forceinline__ unsigned blockScanExcl1024(unsigned v, unsigned* s_tmp, unsigned* total) {
    int tid = threadIdx.x, lane = tid & 31, wid = tid >> 5;
    __syncthreads();
    unsigned inc = warpScanIncl(v);
    if (lane == 31) s_tmp[wid] = inc;
    __syncthreads();
    if (wid == 0) {
        unsigned w = s_tmp[lane];
        unsigned wi = warpScanIncl(w);
        s_tmp[lane] = wi - w;
        if (lane == 31) s_tmp[32] = wi;
    }
    __syncthreads();
    *total = s_tmp[32];
    return inc - v + s_tmp[wid];
}

// ---------------- 1. vertex squared norms (XLA-order) + init m ----------------
__global__ void k_vnorm(const float* __restrict__ image) {
    int idx = blockIdx.x * blockDim.x + threadIdx.x;
    if (idx >= BB * NN) return;
    const float* row = image + (size_t)idx * FF;
    float p[32];
#pragma unroll
    for (int l = 0; l < 32; l++) {
        float a = row[l], c = row[l + 32];
        p[l] = __fadd_rn(__fmul_rn(a, a), __fmul_rn(c, c));
    }
#pragma unroll
    for (int off = 16; off >= 1; off >>= 1) {
#pragma unroll
        for (int l = 0; l < 16; l++) {
            if (l < off) p[l] = __fadd_rn(p[l], p[l + off]);
        }
    }
    g_vn[0][idx] = p[0];
    g_m[0][idx] = idx & (NN - 1);
}

// ---------------- 2. keys (boundary edges pushed to tail) ----------------
__global__ void k_keys(const int* __restrict__ edges, const float* __restrict__ vs) {
    int idx = blockIdx.x * blockDim.x + threadIdx.x;
    int b = idx >> 16, e = idx & (EE - 1);
    if (b >= BB) return;
    int a = edges[(size_t)b * 2 * EE + e];
    int v1 = edges[(size_t)b * 2 * EE + EE + e];
    float c = __fadd_rn(g_vn[b][a], g_vn[b][v1]);
    float ax = vs[((size_t)b * NN + a) * 2 + 0], ay = vs[((size_t)b * NN + a) * 2 + 1];
    float bx = vs[((size_t)b * NN + v1) * 2 + 0], by = vs[((size_t)b * NN + v1) * 2 + 1];
    bool bndA = (ax < 0.05f) | (ax > 0.95f) | (ay < 0.05f) | (ay > 0.95f);
    bool bndB = (bx < 0.05f) | (bx > 0.95f) | (by < 0.05f) | (by > 0.95f);
    unsigned okv = (unsigned)(!(bndA | bndB));
    g_ok[b][e] = (unsigned char)okv;
    // non-ok edges: hi = 0xFFFFFFFF (> any finite +float bits) -> sorted to tail.
    unsigned hi = okv ? __float_as_uint(c) : 0xFFFFFFFFu;
    g_keys[0][b][e] = ((unsigned long long)hi << 32) | (unsigned)e;
}

// ---------------- 3. multi-block stable LSD radix sort: 4 passes x 8-bit ----------------
__global__ void k_count(int p) {
    __shared__ unsigned s_h[256];
    int b = blockIdx.y, blk = blockIdx.x, t = threadIdx.x;
    s_h[t] = 0;
    __syncthreads();
    const unsigned long long* src = g_keys[p & 1][b];
    int sh = 32 + 8 * p;
    unsigned long long k0 = src[blk * 512 + t], k1 = src[blk * 512 + 256 + t];
    atomicAdd(&s_h[(unsigned)(k0 >> sh) & 255u], 1u);
    atomicAdd(&s_h[(unsigned)(k1 >> sh) & 255u], 1u);
    __syncthreads();
    g_hist[b][t * NBLK + blk] = s_h[t];
}

__global__ void __launch_bounds__(1024) k_scan() {
    __shared__ unsigned s_tmp[33];
    int b = blockIdx.x, t = threadIdx.x;
    unsigned v[32]; unsigned sum = 0;
    int base = t * 32;
#pragma unroll
    for (int i = 0; i < 32; i++) { v[i] = g_hist[b][base + i]; sum += v[i]; }
    unsigned tot;
    unsigned ex = blockScanExcl1024(sum, s_tmp, &tot);
    unsigned run = ex;
#pragma unroll
    for (int i = 0; i < 32; i++) { g_histS[b][base + i] = run; run += v[i]; }
}

// last pass writes g_sedge directly (fused gather)
__global__ void __launch_bounds__(256) k_scat(int p, const int* __restrict__ edges, int last) {
    __shared__ unsigned s_wcnt[8 * 256];
    __shared__ unsigned s_pre[8 * 256];
    __shared__ unsigned s_base[256];
    int b = blockIdx.y, blk = blockIdx.x, t = threadIdx.x, lane = t & 31, w = t >> 5;
    const unsigned long long* src = g_keys[p & 1][b];
    unsigned long long* dst = g_keys[(p + 1) & 1][b];
    int sh = 32 + 8 * p;
#pragma unroll
    for (int k = 0; k < 8; k++) s_wcnt[k * 256 + t] = 0;
    s_base[t] = g_histS[b][t * NBLK + blk];
    unsigned long long kk[2] = { src[blk * 512 + t], src[blk * 512 + 256 + t] };
    __syncthreads();
#pragma unroll
    for (int i = 0; i < 2; i++) {
        unsigned d = (unsigned)(kk[i] >> sh) & 255u;
        unsigned m = __match_any_sync(FULLM, d);
        unsigned below = (1u << lane) - 1u;
        unsigned rw = __popc(m & below);
        if (rw == 0) s_wcnt[w * 256 + d] = __popc(m);
        __syncthreads();
        unsigned run = s_base[t];
#pragma unroll
        for (int w2 = 0; w2 < 8; w2++) { s_pre[w2 * 256 + t] = run; run += s_wcnt[w2 * 256 + t]; }
        s_base[t] = run;
        __syncthreads();
        unsigned pos = s_pre[w * 256 + d] + rw;
        if (!last) {
            dst[pos] = kk[i];
        } else {
            unsigned eid = (unsigned)(kk[i] & 0xffffffffu);
            unsigned a = (unsigned)edges[(size_t)b * 2 * EE + eid];
            unsigned v1 = (unsigned)edges[(size_t)b * 2 * EE + EE + eid];
            g_sedge[b][pos] = a | (v1 << 13) | ((unsigned)g_ok[b][eid] << 26);
        }
        if (rw == 0) s_wcnt[w * 256 + d] = 0;
        __syncthreads();
    }
}

// ---------------- 4. greedy collapse: 64-edge windows, symmetric epoch-tag probe ---------
__global__ void k_greedy() {
    __shared__ unsigned char s_mask[NN];
    __shared__ unsigned short s_tagA[NN];   // epoch: vertex used as absorber in window
    __shared__ unsigned short s_tagB[NN];   // epoch: vertex used as kill-target in window
    __shared__ unsigned char  s_own[NN];    // slot id (0..63) of last kill-target writer
    int bb = blockIdx.x, lane = threadIdx.x;
    for (int i = lane; i < NN; i += 32) { s_mask[i] = 1; s_tagA[i] = 0xFFFF; s_tagB[i] = 0xFFFF; }
    __syncwarp();
    int nk = 0;
    const int W = EE / 64;
    unsigned c0 = g_sedge[bb][lane],      c1 = g_sedge[bb][32 + lane];
    unsigned n0 = g_sedge[bb][64 + lane], n1 = g_sedge[bb][96 + lane];
    for (int w = 0; w < W; w++) {
        unsigned p0 = 0, p1 = 0;
        if (w + 2 < W) { p0 = g_sedge[bb][(w + 2) * 64 + lane]; p1 = g_sedge[bb][(w + 2) * 64 + 32 + lane]; }
        int a0 = c0 & 8191, b0 = (c0 >> 13) & 8191, ok0 = (c0 >> 26) & 1;
        int a1 = c1 & 8191, b1 = (c1 >> 13) & 8191, ok1 = (c1 >> 26) & 1;
        int t0 = ok0 && s_mask[a0] && s_mask[b0];
        int t1 = ok1 && s_mask[a1] && s_mask[b1];
        unsigned T0 = __ballot_sync(FULLM, t0);
        unsigned T1 = __ballot_sync(FULLM, t1);
        if (T0 | T1) {
            unsigned short w16 = (unsigned short)w;
            if (t0) { s_tagA[a0] = w16; s_tagB[b0] = w16; s_own[b0] = (unsigned char)lane; }
            if (t1) { s_tagA[a1] = w16; s_tagB[b1] = w16; s_own[b1] = (unsigned char)(32 + lane); }
            __syncwarp();
            // ownership losers republish their kill-target as an absorber tag so that the
            // race winner also sees a hit -> symmetric flagging of duplicate kills.
            int l0 = t0 && (s_own[b0] != (unsigned char)lane);
            int l1 = t1 && (s_own[b1] != (unsigned char)(32 + lane));
            if (l0) s_tagA[b0] = w16;
            if (l1) s_tagA[b1] = w16;
            __syncwarp();
            int f0 = 0, f1 = 0;
            if (t0) f0 = l0 || (s_tagA[b0] == w16) || (s_tagB[a0] == w16);
            if (t1) f1 = l1 || (s_tagA[b1] == w16) || (s_tagB[a1] == w16);
            unsigned I0 = __ballot_sync(FULLM, f0);
            unsigned I1 = __ballot_sync(FULLM, f1);
            int cnt = __popc(T0) + __popc(T1);
            unsigned acc0 = 0, acc1 = 0;
            unsigned below = (1u << lane) - 1u;
            if (!(I0 | I1) && nk + cnt <= TGT) {
                acc0 = T0; acc1 = T1; nk += cnt;
            } else if (!(I0 | I1)) {
                int rem = TGT - nk;
                acc0 = __ballot_sync(FULLM, t0 && (__popc(T0 & below) < rem));
                int rem1 = rem - __popc(T0); if (rem1 < 0) rem1 = 0;
                acc1 = __ballot_sync(FULLM, t1 && (__popc(T1 & below) < rem1));
                nk = TGT;
            } else if (nk + cnt <= TGT) {
                acc0 = T0 & ~I0; acc1 = T1 & ~I1;
                nk += __popc(acc0) + __popc(acc1);
                unsigned TT = I0;
                while (TT) {
                    int t2 = __ffs(TT) - 1; TT &= TT - 1;
                    int at = __shfl_sync(FULLM, a0, t2);
                    int bt = __shfl_sync(FULLM, b0, t2);
                    unsigned conf = __ballot_sync(FULLM,
                        (((acc0 >> lane) & 1) && (b0 == at || b0 == bt)) ||
                        (((acc1 >> lane) & 1) && (b1 == at || b1 == bt)));
                    if (!conf) { acc0 |= 1u << t2; nk++; }
                }
                TT = I1;
                while (TT) {
                    int t2 = __ffs(TT) - 1; TT &= TT - 1;
                    int at = __shfl_sync(FULLM, a1, t2);
                    int bt = __shfl_sync(FULLM, b1, t2);
                    unsigned conf = __ballot_sync(FULLM,
                        (((acc0 >> lane) & 1) && (b0 == at || b0 == bt)) ||
                        (((acc1 >> lane) & 1) && (b1 == at || b1 == bt)));
                    if (!conf) { acc1 |= 1u << t2; nk++; }
                }
            } else {
                unsigned TT = T0;
                while (TT) {
                    int t2 = __ffs(TT) - 1; TT &= TT - 1;
                    int at = __shfl_sync(FULLM, a0, t2);
                    int bt = __shfl_sync(FULLM, b0, t2);
                    unsigned conf = __ballot_sync(FULLM,
                        (((acc0 >> lane) & 1) && (b0 == at || b0 == bt)) ||
                        (((acc1 >> lane) & 1) && (b1 == at || b1 == bt)));
                    if (!conf && nk < TGT) { acc0 |= 1u << t2; nk++; }
                }
                TT = T1;
                while (TT) {
                    int t2 = __ffs(TT) - 1; TT &= TT - 1;
                    int at = __shfl_sync(FULLM, a1, t2);
                    int bt = __shfl_sync(FULLM, b1, t2);
                    unsigned conf = __ballot_sync(FULLM,
                        (((acc0 >> lane) & 1) && (b0 == at || b0 == bt)) ||
                        (((acc1 >> lane) & 1) && (b1 == at || b1 == bt)));
                    if (!conf && nk < TGT) { acc1 |= 1u << t2; nk++; }
                }
            }
            if ((acc0 >> lane) & 1) { s_mask[b0] = 0; g_m[bb][b0] = a0; }
            if ((acc1 >> lane) & 1) { s_mask[b1] = 0; g_m[bb][b1] = a1; }
            __syncwarp();
            if (nk >= TGT) break;
        }
        c0 = n0; c1 = n1; n0 = p0; n1 = p1;
    }
    for (int i = lane; i < NN; i += 32) g_mask[bb][i] = s_mask[i];
}

// ---------------- 5. alive ranks + group CSR ----------------
__global__ void __launch_bounds__(1024) k_compact() {
    __shared__ unsigned s_tmp[33];
    __shared__ int s_cnt[KK];
    __shared__ int s_cur[KK];
    int b = blockIdx.x, tid = threadIdx.x;
    int base = tid * 8;
    unsigned mk[8]; unsigned c = 0;
#pragma unroll
    for (int i = 0; i < 8; i++) { mk[i] = (unsigned)g_mask[b][base + i]; c += mk[i]; }
    unsigned tot;
    unsigned ex = blockScanExcl1024(c, s_tmp, &tot);
    int run = (int)ex;
#pragma unroll
    for (int i = 0; i < 8; i++) { g_rank[b][base + i] = run; run += (int)mk[i]; }
    __syncthreads();
    for (int r = tid; r < KK; r += 1024) s_cnt[r] = 0;
    __syncthreads();
    for (int j = tid; j < NN; j += 1024) {
        int t = g_m[b][j];
        if (g_mask[b][t]) { int r = g_rank[b][t]; if (r < KK) atomicAdd(&s_cnt[r], 1); }
    }
    __syncthreads();
    int i4 = tid * 4; unsigned cv[4]; unsigned sum = 0;
#pragma unroll
    for (int i = 0; i < 4; i++) { cv[i] = (unsigned)s_cnt[i4 + i]; sum += cv[i]; }
    unsigned tot2;
    unsigned ex2 = blockScanExcl1024(sum, s_tmp, &tot2);
    int run2 = (int)ex2;
#pragma unroll
    for (int i = 0; i < 4; i++) { g_gstart[b][i4 + i] = run2; s_cur[i4 + i] = run2; run2 += (int)cv[i]; }
    if (tid == 1023) g_gstart[b][KK] = run2;
    __syncthreads();
    for (int j = tid; j < NN; j += 1024) {
        int t = g_m[b][j];
        if (g_mask[b][t]) {
            int r = g_rank[b][t];
            if (r < KK) { int pos = atomicAdd(&s_cur[r], 1); g_gsrc[b][pos] = (unsigned short)j; }
        }
    }
}

// ---------------- 6. pack A (f32 0/1) -> row-major bits via warp ballot ----------------
__global__ void __launch_bounds__(256) k_pack(const float* __restrict__ A) {
    int gw = (blockIdx.x * 256 + threadIdx.x) >> 5;
    int lane = threadIdx.x & 31;
    const float* base = A + (size_t)gw * 1024;
    unsigned myw = 0;
#pragma unroll
    for (int t = 0; t < 32; t++) {
        float v = base[t * 32 + lane];
        unsigned bal = __ballot_sync(FULLM, v != 0.0f);
        if (lane == t) myw = bal;
    }
    ((unsigned*)g_Ab)[(size_t)gw * 32 + lane] = myw;
}

// ---------------- 7. G1[r] = OR of A-bit rows in group(r)  (row merge) ----------------
__global__ void __launch_bounds__(1024) k_G1() {
    int b = blockIdx.y;
    int c = blockIdx.x * 4 + (threadIdx.x >> 8);
    int w = threadIdx.x & 255;
    int s = g_gstart[b][c], e = g_gstart[b][c + 1];
    unsigned v = 0;
    for (int i = s; i < e; i++) v |= g_Ab[b][g_gsrc[b][i]][w];
    g_G1[b][c][w] = v;
}

// ---------------- 8. bit transpose G1 (K x N) -> G1T (N x K) ----------------
__global__ void __launch_bounds__(1024) k_transT() {
    __shared__ __align__(16) unsigned wt[256 * 5];
    __shared__ __align__(16) unsigned outS[1024];
    int b = blockIdx.z, ct = blockIdx.y, jt = blockIdx.x;
    int tid = threadIdx.x;
    {
        int r = tid >> 2, w4 = tid & 3;
        wt[r * 5 + w4] = g_G1[b][ct * 256 + r][jt * 4 + w4];
    }
    __syncthreads();
    int w = tid >> 5, lane = tid & 31;
    int jw = w >> 3, iw = w & 7;
    unsigned s = wt[(iw * 32 + lane) * 5 + jw];
    unsigned myword = 0;
#pragma unroll 1
    for (int k = 0; k < 32; k++) {
        unsigned bt = __ballot_sync(FULLM, (s >> k) & 1);
        if (lane == k) myword = bt;
    }
    outS[(jw * 32 + lane) * 8 + iw] = myword;
    __syncthreads();
    int j = tid >> 3, ww = tid & 7;
    g_G1T[b][jt * 128 + j][ct * 8 + ww] = outS[tid];
}

// ---------------- 9. G2[c] = OR of G1T rows in group(c)  (col merge) ----------------
__global__ void __launch_bounds__(1024) k_G2() {
    int b = blockIdx.y;
    int r = blockIdx.x * 8 + (threadIdx.x >> 7);
    int w = threadIdx.x & 127;
    int s = g_gstart[b][r], e = g_gstart[b][r + 1];
    unsigned v = 0;
    for (int i = s; i < e; i++) v |= g_G1T[b][g_gsrc[b][i]][w];
    g_G2[b][r][w] = v;
}

// ---------------- 10. final K x K bit transpose: G2 -> M2 ----------------
__global__ void __launch_bounds__(1024) k_transKK() {
    __shared__ __align__(16) unsigned wt[256 * 5];
    __shared__ __align__(16) unsigned outS[1024];
    int b = blockIdx.z, ct = blockIdx.y, jt = blockIdx.x;
    int tid = threadIdx.x;
    {
        int r = tid >> 2, w4 = tid & 3;
        wt[r * 5 + w4] = g_G2[b][ct * 256 + r][jt * 4 + w4];
    }
    __syncthreads();
    int w = tid >> 5, lane = tid & 31;
    int jw = w >> 3, iw = w & 7;
    unsigned s = wt[(iw * 32 + lane) * 5 + jw];
    unsigned myword = 0;
#pragma unroll 1
    for (int k = 0; k < 32; k++) {
        unsigned bt = __ballot_sync(FULLM, (s >> k) & 1);
        if (lane == k) myword = bt;
    }
    outS[(jw * 32 + lane) * 8 + iw] = myword;
    __syncthreads();
    int j = tid >> 3, ww = tid & 7;
    g_M2[b][jt * 128 + j][ct * 8 + ww] = outS[tid];
}

// ---------------- 11. expand bits -> float (diag cleared) + pooled features ----------
__global__ void k_expandfeat(const float* __restrict__ image, float* __restrict__ out) {
    int b = blockIdx.y;
    if (blockIdx.x < 16384) {
        int idx = blockIdx.x * 256 + threadIdx.x;
        int r = idx >> 10;
        int c4 = (idx & 1023) << 2;
        unsigned wv = g_M2[b][r][c4 >> 5];
        int sh = c4 & 31;
        float4 o;
        o.x = (((wv >> (sh + 0)) & 1) && (r != c4 + 0)) ? 1.f : 0.f;
        o.y = (((wv >> (sh + 1)) & 1) && (r != c4 + 1)) ? 1.f : 0.f;
        o.z = (((wv >> (sh + 2)) & 1) && (r != c4 + 2)) ? 1.f : 0.f;
        o.w = (((wv >> (sh + 3)) & 1) && (r != c4 + 3)) ? 1.f : 0.f;
        ((float4*)out)[((size_t)b * KK + r) * (KK / 4) + (idx & 1023)] = o;
    } else {
        int idx = (blockIdx.x - 16384) * 256 + threadIdx.x;
        int f = idx & (FF - 1);
        int r = idx >> 6;
        int s = g_gstart[b][r], e = g_gstart[b][r + 1];
        float acc = 0.f;
        for (int i = s; i < e; i++) {
            int j = g_gsrc[b][i];
            acc += image[((size_t)b * NN + j) * FF + f];
        }
        out[(size_t)BB * KK * KK + ((size_t)b * KK + r) * FF + f] = acc;
    }
}

// ---------------- launch ----------------
extern "C" void kernel_launch(void* const* d_in, const int* in_sizes, int n_in,
                              void* d_out, int out_size) {
    const float* adj = (const float*)d_in[0];
    const float* image = (const float*)d_in[1];
    const float* vs = (const float*)d_in[2];
    const int* edges = (const int*)d_in[3];
    float* out = (float*)d_out;

    static cudaStream_t s1 = nullptr;
    static cudaEvent_t evF = nullptr, evJ = nullptr;
    if (!s1) {
        cudaStreamCreateWithFlags(&s1, cudaStreamNonBlocking);
        cudaEventCreateWithFlags(&evF, cudaEventDisableTiming);
        cudaEventCreateWithFlags(&evJ, cudaEventDisableTiming);
    }

    // fork: pack (1GB adj read) overlaps the whole cost/sort/greedy chain
    cudaEventRecord(evF, 0);
    cudaStreamWaitEvent(s1, evF, 0);
    k_pack<<<32768, 256, 0, s1>>>(adj);

    k_vnorm<<<(BB * NN) / 256, 256>>>(image);
    k_keys<<<(BB * EE) / 256, 256>>>(edges, vs);
    for (int p = 0; p < 4; p++) {
        k_count<<<dim3(NBLK, BB), 256>>>(p);
        k_scan<<<BB, 1024>>>();
        k_scat<<<dim3(NBLK, BB), 256>>>(p, edges, p == 3);
    }
    k_greedy<<<BB, 32>>>();
    k_compact<<<BB, 1024>>>();

    // join pack before merges
    cudaEventRecord(evJ, s1);
    cudaStreamWaitEvent(0, evJ, 0);

    k_G1<<<dim3(KK / 4, BB), 1024>>>();
    k_transT<<<dim3(NN / 128, KK / 256, BB), 1024>>>();
    k_G2<<<dim3(KK / 8, BB), 1024>>>();
    k_transKK<<<dim3(KK / 128, KK / 256, BB), 1024>>>();
    k_expandfeat<<<dim3(16384 + (KK * FF) / 256, BB), 256>>>(image, out);
}